// round 1
// baseline (speedup 1.0000x reference)
#include <cuda_runtime.h>

// Problem constants
constexpr int B    = 16;
constexpr int C    = 512;
constexpr int HEAD = 8;
constexpr int D    = 64;     // C / HEAD
constexpr int N    = 1024;   // 32*32
constexpr int IMG  = 32;

// Scratch (no allocations allowed -> __device__ globals)
__device__ float g_q[B * C * N];
__device__ float g_k[B * C * N];
__device__ float g_v[B * C * N];

// ---------------------------------------------------------------------------
// Kernel 1: QKV projection.  out[b, o, n] = sum_c W[o,c] * x[b,c,n] + bias[o]
// grid: (N/64, C/64, 3*B), block: 16x16, each thread computes 4x4 outputs.
// ---------------------------------------------------------------------------
__global__ __launch_bounds__(256) void qkv_kernel(
    const float* __restrict__ x,
    const float* __restrict__ Wq, const float* __restrict__ bq,
    const float* __restrict__ Wk, const float* __restrict__ bk,
    const float* __restrict__ Wv, const float* __restrict__ bv)
{
    __shared__ float Ws[64][17];   // [o][c] tile, padded
    __shared__ float Xs[16][64];   // [c][n] tile

    const int b     = blockIdx.z % B;
    const int which = blockIdx.z / B;
    const float* W    = (which == 0) ? Wq : (which == 1) ? Wk : Wv;
    const float* bias = (which == 0) ? bq : (which == 1) ? bk : bv;
    float* out        = (which == 0) ? g_q : (which == 1) ? g_k : g_v;

    const int o0 = blockIdx.y * 64;
    const int n0 = blockIdx.x * 64;
    const int tx = threadIdx.x, ty = threadIdx.y;
    const int t  = ty * 16 + tx;

    float acc[4][4] = {};

    for (int c0 = 0; c0 < C; c0 += 16) {
        #pragma unroll
        for (int k = 0; k < 4; k++) {
            int idx = t + k * 256;
            int row = idx >> 4, col = idx & 15;
            Ws[row][col] = W[(o0 + row) * C + c0 + col];
        }
        #pragma unroll
        for (int k = 0; k < 4; k++) {
            int idx = t + k * 256;
            int row = idx >> 6, col = idx & 63;
            Xs[row][col] = x[((b * C) + c0 + row) * N + n0 + col];
        }
        __syncthreads();
        #pragma unroll
        for (int kk = 0; kk < 16; kk++) {
            float a[4], bb[4];
            #pragma unroll
            for (int i = 0; i < 4; i++) a[i] = Ws[ty * 4 + i][kk];
            #pragma unroll
            for (int j = 0; j < 4; j++) bb[j] = Xs[kk][tx * 4 + j];
            #pragma unroll
            for (int i = 0; i < 4; i++)
                #pragma unroll
                for (int j = 0; j < 4; j++)
                    acc[i][j] += a[i] * bb[j];
        }
        __syncthreads();
    }

    #pragma unroll
    for (int i = 0; i < 4; i++) {
        float bo = bias[o0 + ty * 4 + i];
        float* orow = out + ((size_t)(b * C) + o0 + ty * 4 + i) * N + n0 + tx * 4;
        #pragma unroll
        for (int j = 0; j < 4; j++) orow[j] = acc[i][j] + bo;
    }
}

// ---------------------------------------------------------------------------
// Kernel 2: flash-style attention for one (b, h, 64-query-row tile).
// E[i,j] = sum_{d'=0..127} A[d',i] * Bm[d',j],  A=[q;pos], Bm=[k;q]
// Online softmax over j, O[m,dd] = sum_j P[m,j] v[dd,j], out = O/l + x.
// Note: reg_qk / reg_v groups are dropped by out[:, :head] -> skipped entirely.
// grid: (N/64, HEAD, B), block: 256 threads (16x16 logical).
// ---------------------------------------------------------------------------
constexpr int SMEM_ATTN = (128 * 64 + 128 * 64 + 64 * 68 + 64 * 68) * 4;

__global__ __launch_bounds__(256) void attn_kernel(
    const float* __restrict__ x,
    const float* __restrict__ rel_h,
    const float* __restrict__ rel_w,
    float* __restrict__ out)
{
    extern __shared__ float smem[];
    float* As = smem;                 // [128][64]  A-side (resident)
    float* Bs = As + 128 * 64;        // [128][64]  B-side (per j-tile)
    float* Vs = Bs + 128 * 64;        // [64][68]   V transposed: Vs[j][dd]
    float* Ps = Vs + 64 * 68;         // [64][68]   P tile / output staging

    const int i0 = blockIdx.x * 64;
    const int h  = blockIdx.y;
    const int b  = blockIdx.z;
    const int t  = threadIdx.x;
    const int tx = t & 15, ty = t >> 4;

    const float* qb = g_q + (size_t)(b * C + h * D) * N;
    const float* kb = g_k + (size_t)(b * C + h * D) * N;
    const float* vb = g_v + (size_t)(b * C + h * D) * N;

    // Load A-side: rows [0,64) = q columns i0.., rows [64,128) = pos columns i0..
    for (int idx = t; idx < 64 * 64; idx += 256) {
        int dd = idx >> 6, col = idx & 63;
        int n  = i0 + col;
        As[dd * 64 + col]        = qb[dd * N + n];
        As[(64 + dd) * 64 + col] = rel_h[(h * D + dd) * IMG + (n & 31)]
                                 + rel_w[(h * D + dd) * IMG + (n >> 5)];
    }

    float m_run[4], l_run[4];
    float o_acc[4][4] = {};
    #pragma unroll
    for (int i = 0; i < 4; i++) { m_run[i] = -1e30f; l_run[i] = 0.f; }

    for (int j0 = 0; j0 < N; j0 += 64) {
        // Load B-side (k then q) and V (transposed)
        for (int idx = t; idx < 64 * 64; idx += 256) {
            int dd = idx >> 6, col = idx & 63;
            Bs[dd * 64 + col]        = kb[dd * N + j0 + col];
            Bs[(64 + dd) * 64 + col] = qb[dd * N + j0 + col];
            Vs[col * 68 + dd]        = vb[dd * N + j0 + col];
        }
        __syncthreads();

        // S tile: 4x4 per thread, inner dim 128
        float s[4][4] = {};
        #pragma unroll 8
        for (int dp = 0; dp < 128; dp++) {
            float4 a4 = *reinterpret_cast<const float4*>(&As[dp * 64 + ty * 4]);
            float4 b4 = *reinterpret_cast<const float4*>(&Bs[dp * 64 + tx * 4]);
            float a[4] = {a4.x, a4.y, a4.z, a4.w};
            float bb[4] = {b4.x, b4.y, b4.z, b4.w};
            #pragma unroll
            for (int i = 0; i < 4; i++)
                #pragma unroll
                for (int j = 0; j < 4; j++)
                    s[i][j] += a[i] * bb[j];
        }

        // Online softmax per row (reduce across the 16 tx lanes; they are the
        // low/high half of a warp, so xor-shuffles with offsets 8..1 stay inside)
        #pragma unroll
        for (int i = 0; i < 4; i++) {
            int r = ty * 4 + i;
            float mx = fmaxf(fmaxf(s[i][0], s[i][1]), fmaxf(s[i][2], s[i][3]));
            #pragma unroll
            for (int off = 8; off > 0; off >>= 1)
                mx = fmaxf(mx, __shfl_xor_sync(0xffffffffu, mx, off));
            float m_new = fmaxf(m_run[i], mx);
            float scale = __expf(m_run[i] - m_new);
            float psum = 0.f;
            #pragma unroll
            for (int j = 0; j < 4; j++) {
                float p = __expf(s[i][j] - m_new);
                Ps[r * 68 + tx * 4 + j] = p;
                psum += p;
            }
            #pragma unroll
            for (int off = 8; off > 0; off >>= 1)
                psum += __shfl_xor_sync(0xffffffffu, psum, off);
            l_run[i] = l_run[i] * scale + psum;
            m_run[i] = m_new;
            #pragma unroll
            for (int j = 0; j < 4; j++) o_acc[i][j] *= scale;
        }
        __syncthreads();

        // PV: O[r, c] += sum_n P[r,n] * V[c,n]   (Vs holds V transposed: Vs[n][c])
        #pragma unroll 8
        for (int n = 0; n < 64; n++) {
            float4 v4 = *reinterpret_cast<const float4*>(&Vs[n * 68 + tx * 4]);
            float vv[4] = {v4.x, v4.y, v4.z, v4.w};
            float a[4];
            #pragma unroll
            for (int i = 0; i < 4; i++) a[i] = Ps[(ty * 4 + i) * 68 + n];
            #pragma unroll
            for (int i = 0; i < 4; i++)
                #pragma unroll
                for (int j = 0; j < 4; j++)
                    o_acc[i][j] += a[i] * vv[j];
        }
        __syncthreads();
    }

    // Normalize and stage to smem, then coalesced write (+x residual)
    #pragma unroll
    for (int i = 0; i < 4; i++) {
        float inv_l = 1.f / l_run[i];
        #pragma unroll
        for (int j = 0; j < 4; j++)
            Ps[(ty * 4 + i) * 68 + tx * 4 + j] = o_acc[i][j] * inv_l;
    }
    __syncthreads();

    for (int idx = t; idx < 64 * 64; idx += 256) {
        int c = idx >> 6, mm = idx & 63;
        size_t gi = ((size_t)(b * C) + h * D + c) * N + i0 + mm;
        out[gi] = Ps[mm * 68 + c] + x[gi];
    }
}

// ---------------------------------------------------------------------------
extern "C" void kernel_launch(void* const* d_in, const int* in_sizes, int n_in,
                              void* d_out, int out_size)
{
    const float* x     = (const float*)d_in[0];
    const float* Wq    = (const float*)d_in[1];
    const float* bq    = (const float*)d_in[2];
    const float* Wk    = (const float*)d_in[3];
    const float* bk    = (const float*)d_in[4];
    const float* Wv    = (const float*)d_in[5];
    const float* bv    = (const float*)d_in[6];
    const float* rel_h = (const float*)d_in[7];
    const float* rel_w = (const float*)d_in[8];
    // d_in[9] (reg_qk) and d_in[10] (reg_v) are dead: their group is dropped
    // by out[:, :head] before the final reshape.
    float* out = (float*)d_out;

    dim3 grid1(N / 64, C / 64, 3 * B);
    qkv_kernel<<<grid1, dim3(16, 16)>>>(x, Wq, bq, Wk, bk, Wv, bv);

    cudaFuncSetAttribute(attn_kernel,
                         cudaFuncAttributeMaxDynamicSharedMemorySize, SMEM_ATTN);
    dim3 grid2(N / 64, HEAD, B);
    attn_kernel<<<grid2, 256, SMEM_ATTN>>>(x, rel_h, rel_w, out);
}

// round 4
// speedup vs baseline: 2.5624x; 2.5624x over previous
#include <cuda_runtime.h>
#include <cstdint>

// Problem constants
constexpr int B    = 16;
constexpr int C    = 512;
constexpr int HEAD = 8;
constexpr int D    = 64;     // C / HEAD
constexpr int N    = 1024;   // 32*32
constexpr int IMG  = 32;

// Scratch (no allocations allowed -> __device__ globals)
__device__ float g_q[B * C * N];
__device__ float g_k[B * C * N];
__device__ float g_v[B * C * N];

// ---------------------------------------------------------------------------
// TF32 helpers
// ---------------------------------------------------------------------------
__device__ __forceinline__ uint32_t f2tf(float f) {
    uint32_t u;
    asm("cvt.rna.tf32.f32 %0, %1;" : "=r"(u) : "f"(f));
    return u;
}

__device__ __forceinline__ void mma_tf32(float* c,
                                         uint32_t a0, uint32_t a1, uint32_t a2, uint32_t a3,
                                         uint32_t b0, uint32_t b1) {
    asm volatile(
        "mma.sync.aligned.m16n8k8.row.col.f32.tf32.tf32.f32 "
        "{%0,%1,%2,%3}, {%4,%5,%6,%7}, {%8,%9}, {%0,%1,%2,%3};"
        : "+f"(c[0]), "+f"(c[1]), "+f"(c[2]), "+f"(c[3])
        : "r"(a0), "r"(a1), "r"(a2), "r"(a3), "r"(b0), "r"(b1));
}

// ---------------------------------------------------------------------------
// Kernel 1: QKV projection via tf32 mma.
// out[b,o,n] = sum_c W[o,c] x[b,c,n] + bias[o]
// Block tile: 128(o) x 128(n), BK=32. 8 warps, each warp does 32x64.
// grid: (N/128, C/128, 3*B), 256 threads.
// ---------------------------------------------------------------------------
__global__ __launch_bounds__(256) void qkv_mma(
    const float* __restrict__ x,
    const float* __restrict__ Wq, const float* __restrict__ bq,
    const float* __restrict__ Wk, const float* __restrict__ bk,
    const float* __restrict__ Wv, const float* __restrict__ bv)
{
    __shared__ uint32_t Ws[32 * 133];   // [c][o], tf32 bits, stride 133
    __shared__ uint32_t Xs[32 * 132];   // [c][n], tf32 bits, stride 132

    const int bz = blockIdx.z;
    const int b = bz % B;
    const int which = bz / B;
    const float* Wm   = (which == 0) ? Wq : (which == 1) ? Wk : Wv;
    const float* bias = (which == 0) ? bq : (which == 1) ? bk : bv;
    float* outp       = (which == 0) ? g_q : (which == 1) ? g_k : g_v;

    const int o0 = blockIdx.y * 128;
    const int n0 = blockIdx.x * 128;
    const int t = threadIdx.x;
    const int lane = t & 31, wid = t >> 5;
    const int g = lane >> 2, t4 = lane & 3;
    const int wm = (wid >> 1) * 32;   // warp row origin (o)
    const int wn = (wid & 1) * 64;    // warp col origin (n)

    float acc[2][8][4] = {};

    for (int c0 = 0; c0 < C; c0 += 32) {
        // Load W tile (transposed into Ws[c][o]), coalesced along c
        #pragma unroll
        for (int kl = 0; kl < 4; kl++) {
            int o = (t >> 3) + kl * 32;
            int c = (t & 7) * 4;
            float4 w4 = *(const float4*)&Wm[(size_t)(o0 + o) * C + c0 + c];
            Ws[(c + 0) * 133 + o] = f2tf(w4.x);
            Ws[(c + 1) * 133 + o] = f2tf(w4.y);
            Ws[(c + 2) * 133 + o] = f2tf(w4.z);
            Ws[(c + 3) * 133 + o] = f2tf(w4.w);
        }
        // Load X tile (Xs[c][n]), coalesced along n
        #pragma unroll
        for (int kl = 0; kl < 4; kl++) {
            int c = (t >> 5) + kl * 8;
            int n = (t & 31) * 4;
            float4 x4 = *(const float4*)&x[((size_t)b * C + c0 + c) * N + n0 + n];
            *(uint4*)&Xs[c * 132 + n] =
                make_uint4(f2tf(x4.x), f2tf(x4.y), f2tf(x4.z), f2tf(x4.w));
        }
        __syncthreads();

        #pragma unroll
        for (int kk = 0; kk < 4; kk++) {
            int k0 = kk * 8;
            uint32_t a[2][4];
            #pragma unroll
            for (int i = 0; i < 2; i++) {
                int m = wm + i * 16;
                a[i][0] = Ws[(k0 + t4) * 133 + m + g];
                a[i][1] = Ws[(k0 + t4) * 133 + m + g + 8];
                a[i][2] = Ws[(k0 + t4 + 4) * 133 + m + g];
                a[i][3] = Ws[(k0 + t4 + 4) * 133 + m + g + 8];
            }
            #pragma unroll
            for (int jf = 0; jf < 8; jf++) {
                uint32_t b0 = Xs[(k0 + t4) * 132 + wn + jf * 8 + g];
                uint32_t b1 = Xs[(k0 + t4 + 4) * 132 + wn + jf * 8 + g];
                mma_tf32(acc[0][jf], a[0][0], a[0][1], a[0][2], a[0][3], b0, b1);
                mma_tf32(acc[1][jf], a[1][0], a[1][1], a[1][2], a[1][3], b0, b1);
            }
        }
        __syncthreads();
    }

    // Epilogue: add bias, store fp32
    #pragma unroll
    for (int i = 0; i < 2; i++) {
        int o_lo = o0 + wm + i * 16 + g;
        float b_lo = bias[o_lo], b_hi = bias[o_lo + 8];
        #pragma unroll
        for (int jf = 0; jf < 8; jf++) {
            int n = n0 + wn + jf * 8 + 2 * t4;
            float2 v0 = {acc[i][jf][0] + b_lo, acc[i][jf][1] + b_lo};
            float2 v1 = {acc[i][jf][2] + b_hi, acc[i][jf][3] + b_hi};
            *(float2*)&outp[((size_t)b * C + o_lo) * N + n] = v0;
            *(float2*)&outp[((size_t)b * C + o_lo + 8) * N + n] = v1;
        }
    }
}

// ---------------------------------------------------------------------------
// Kernel 2: flash attention via tf32 mma.
// E[i,j] = sum_{d'<128} A[d',i] * Bm[d',j],  A=[q;pos], Bm=[k;q]
// Block: 128 queries (i), loop over 64-key j-tiles. 8 warps, each warp owns
// 16 query rows x 64 cols -> softmax fully warp-local. P->A-frag via shfl.
// grid: (N/128, HEAD, B), 256 threads.
// ---------------------------------------------------------------------------
constexpr int AS_STRIDE = 132;  // uint32 elems
constexpr int BS_STRIDE = 68;
constexpr int VS_STRIDE = 69;
constexpr int OS_STRIDE = 69;
constexpr int SMEM_ATTN = (128 * AS_STRIDE + 128 * BS_STRIDE + 64 * VS_STRIDE) * 4;

__global__ __launch_bounds__(256) void attn_mma(
    const float* __restrict__ x,
    const float* __restrict__ rel_h,
    const float* __restrict__ rel_w,
    float* __restrict__ out)
{
    extern __shared__ uint32_t smem[];
    uint32_t* As = smem;                         // [128 k][128 i] tf32
    uint32_t* Bs = As + 128 * AS_STRIDE;         // [128 k][64 j]  tf32
    uint32_t* Vs = Bs + 128 * BS_STRIDE;         // [64 j][64 dd]  tf32
    float*    Os = (float*)As;                   // reuse: [128 i][64 dd] stride 69

    const int i0 = blockIdx.x * 128;
    const int h  = blockIdx.y;
    const int b  = blockIdx.z;
    const int t  = threadIdx.x;
    const int lane = t & 31, wid = t >> 5;
    const int g = lane >> 2, t4 = lane & 3;
    const int iw = wid * 16;   // warp's query-row base within block

    const float* qb = g_q + (size_t)(b * C + h * D) * N;
    const float* kb = g_k + (size_t)(b * C + h * D) * N;
    const float* vb = g_v + (size_t)(b * C + h * D) * N;

    // ---- Load A-side: rows [0,64)=q, [64,128)=pos, cols = queries i0..i0+127
    {
        int col = (t & 31) * 4;
        int hh = col & 31;           // i0 is a multiple of 128, col 4-aligned
        int ww = (i0 + col) >> 5;
        #pragma unroll
        for (int r = 0; r < 8; r++) {
            int dd = (t >> 5) + r * 8;   // 0..63
            float4 q4 = *(const float4*)&qb[(size_t)dd * N + i0 + col];
            *(uint4*)&As[dd * AS_STRIDE + col] =
                make_uint4(f2tf(q4.x), f2tf(q4.y), f2tf(q4.z), f2tf(q4.w));
            const float* rh = &rel_h[(h * D + dd) * IMG + hh];
            float rw = rel_w[(h * D + dd) * IMG + ww];
            *(uint4*)&As[(64 + dd) * AS_STRIDE + col] =
                make_uint4(f2tf(rh[0] + rw), f2tf(rh[1] + rw),
                           f2tf(rh[2] + rw), f2tf(rh[3] + rw));
        }
    }

    float m0 = -1e30f, m1 = -1e30f, l0 = 0.f, l1 = 0.f;
    float o_acc[8][4] = {};

    for (int j0 = 0; j0 < N; j0 += 64) {
        __syncthreads();   // previous iteration finished reading Bs/Vs
        // ---- Load B-side: rows [0,64)=k, [64,128)=q, cols = keys j0..j0+63
        {
            int col = (t & 15) * 4;
            #pragma unroll
            for (int r = 0; r < 4; r++) {
                int dd = (t >> 4) + r * 16;   // 0..63
                float4 k4 = *(const float4*)&kb[(size_t)dd * N + j0 + col];
                *(uint4*)&Bs[dd * BS_STRIDE + col] =
                    make_uint4(f2tf(k4.x), f2tf(k4.y), f2tf(k4.z), f2tf(k4.w));
                float4 q4 = *(const float4*)&qb[(size_t)dd * N + j0 + col];
                *(uint4*)&Bs[(64 + dd) * BS_STRIDE + col] =
                    make_uint4(f2tf(q4.x), f2tf(q4.y), f2tf(q4.z), f2tf(q4.w));
            }
        }
        // ---- Load V transposed: Vs[j][dd]
        {
            int col = (t & 15) * 4;
            #pragma unroll
            for (int r = 0; r < 4; r++) {
                int dd = (t >> 4) + r * 16;
                float4 v4 = *(const float4*)&vb[(size_t)dd * N + j0 + col];
                Vs[(col + 0) * VS_STRIDE + dd] = f2tf(v4.x);
                Vs[(col + 1) * VS_STRIDE + dd] = f2tf(v4.y);
                Vs[(col + 2) * VS_STRIDE + dd] = f2tf(v4.z);
                Vs[(col + 3) * VS_STRIDE + dd] = f2tf(v4.w);
            }
        }
        __syncthreads();

        // ---- S = A^T B  (warp tile 16 x 64), inner dim 128
        float s[8][4] = {};
        #pragma unroll
        for (int kk = 0; kk < 16; kk++) {
            int k0 = kk * 8;
            uint32_t a0 = As[(k0 + t4) * AS_STRIDE + iw + g];
            uint32_t a1 = As[(k0 + t4) * AS_STRIDE + iw + g + 8];
            uint32_t a2 = As[(k0 + t4 + 4) * AS_STRIDE + iw + g];
            uint32_t a3 = As[(k0 + t4 + 4) * AS_STRIDE + iw + g + 8];
            #pragma unroll
            for (int jf = 0; jf < 8; jf++) {
                uint32_t b0 = Bs[(k0 + t4) * BS_STRIDE + jf * 8 + g];
                uint32_t b1 = Bs[(k0 + t4 + 4) * BS_STRIDE + jf * 8 + g];
                mma_tf32(s[jf], a0, a1, a2, a3, b0, b1);
            }
        }

        // ---- Online softmax (warp-local; rows g and g+8)
        float mx0 = -1e30f, mx1 = -1e30f;
        #pragma unroll
        for (int jf = 0; jf < 8; jf++) {
            mx0 = fmaxf(mx0, fmaxf(s[jf][0], s[jf][1]));
            mx1 = fmaxf(mx1, fmaxf(s[jf][2], s[jf][3]));
        }
        #pragma unroll
        for (int off = 1; off <= 2; off <<= 1) {
            mx0 = fmaxf(mx0, __shfl_xor_sync(0xffffffffu, mx0, off));
            mx1 = fmaxf(mx1, __shfl_xor_sync(0xffffffffu, mx1, off));
        }
        float mn0 = fmaxf(m0, mx0), mn1 = fmaxf(m1, mx1);
        float sc0 = __expf(m0 - mn0), sc1 = __expf(m1 - mn1);
        float ls0 = 0.f, ls1 = 0.f;
        #pragma unroll
        for (int jf = 0; jf < 8; jf++) {
            // exp, round to tf32 in place (l accumulates the rounded values)
            float p;
            p = __uint_as_float(f2tf(__expf(s[jf][0] - mn0))); s[jf][0] = p; ls0 += p;
            p = __uint_as_float(f2tf(__expf(s[jf][1] - mn0))); s[jf][1] = p; ls0 += p;
            p = __uint_as_float(f2tf(__expf(s[jf][2] - mn1))); s[jf][2] = p; ls1 += p;
            p = __uint_as_float(f2tf(__expf(s[jf][3] - mn1))); s[jf][3] = p; ls1 += p;
        }
        #pragma unroll
        for (int off = 1; off <= 2; off <<= 1) {
            ls0 += __shfl_xor_sync(0xffffffffu, ls0, off);
            ls1 += __shfl_xor_sync(0xffffffffu, ls1, off);
        }
        l0 = l0 * sc0 + ls0;
        l1 = l1 * sc1 + ls1;
        m0 = mn0; m1 = mn1;
        #pragma unroll
        for (int df = 0; df < 8; df++) {
            o_acc[df][0] *= sc0; o_acc[df][1] *= sc0;
            o_acc[df][2] *= sc1; o_acc[df][3] *= sc1;
        }

        // ---- PV: O[m,dd] += P[m,j] V[j,dd].  A-frags from P via shuffles.
        const int srcb = lane & ~3;
        const int s_lo = srcb + (t4 >> 1);
        const bool odd = (t4 & 1);
        #pragma unroll
        for (int jq = 0; jq < 8; jq++) {
            uint32_t c0 = __float_as_uint(s[jq][0]);
            uint32_t c1 = __float_as_uint(s[jq][1]);
            uint32_t c2 = __float_as_uint(s[jq][2]);
            uint32_t c3 = __float_as_uint(s[jq][3]);
            uint32_t e, o_;
            e  = __shfl_sync(0xffffffffu, c0, s_lo);
            o_ = __shfl_sync(0xffffffffu, c1, s_lo);
            uint32_t a0 = odd ? o_ : e;
            e  = __shfl_sync(0xffffffffu, c0, s_lo + 2);
            o_ = __shfl_sync(0xffffffffu, c1, s_lo + 2);
            uint32_t a2 = odd ? o_ : e;
            e  = __shfl_sync(0xffffffffu, c2, s_lo);
            o_ = __shfl_sync(0xffffffffu, c3, s_lo);
            uint32_t a1 = odd ? o_ : e;
            e  = __shfl_sync(0xffffffffu, c2, s_lo + 2);
            o_ = __shfl_sync(0xffffffffu, c3, s_lo + 2);
            uint32_t a3 = odd ? o_ : e;
            #pragma unroll
            for (int df = 0; df < 8; df++) {
                uint32_t b0 = Vs[(jq * 8 + t4) * VS_STRIDE + df * 8 + g];
                uint32_t b1 = Vs[(jq * 8 + t4 + 4) * VS_STRIDE + df * 8 + g];
                mma_tf32(o_acc[df], a0, a1, a2, a3, b0, b1);
            }
        }
    }

    // ---- Normalize, stage to smem (reuse As region), coalesced +x write
    __syncthreads();   // all warps done reading As/Bs/Vs
    float inv0 = 1.f / l0, inv1 = 1.f / l1;
    #pragma unroll
    for (int df = 0; df < 8; df++) {
        int dd = df * 8 + 2 * t4;
        Os[(iw + g) * OS_STRIDE + dd]         = o_acc[df][0] * inv0;
        Os[(iw + g) * OS_STRIDE + dd + 1]     = o_acc[df][1] * inv0;
        Os[(iw + g + 8) * OS_STRIDE + dd]     = o_acc[df][2] * inv1;
        Os[(iw + g + 8) * OS_STRIDE + dd + 1] = o_acc[df][3] * inv1;
    }
    __syncthreads();

    for (int idx = t; idx < 128 * 64; idx += 256) {
        int dd = idx >> 7, mm = idx & 127;
        size_t gi = ((size_t)(b * C) + h * D + dd) * N + i0 + mm;
        out[gi] = Os[mm * OS_STRIDE + dd] + x[gi];
    }
}

// ---------------------------------------------------------------------------
extern "C" void kernel_launch(void* const* d_in, const int* in_sizes, int n_in,
                              void* d_out, int out_size)
{
    const float* x     = (const float*)d_in[0];
    const float* Wq    = (const float*)d_in[1];
    const float* bq    = (const float*)d_in[2];
    const float* Wk    = (const float*)d_in[3];
    const float* bk    = (const float*)d_in[4];
    const float* Wv    = (const float*)d_in[5];
    const float* bv    = (const float*)d_in[6];
    const float* rel_h = (const float*)d_in[7];
    const float* rel_w = (const float*)d_in[8];
    // d_in[9] (reg_qk) and d_in[10] (reg_v) are dead: that group is dropped
    // by out[:, :head].
    float* out = (float*)d_out;

    dim3 grid1(N / 128, C / 128, 3 * B);
    qkv_mma<<<grid1, 256>>>(x, Wq, bq, Wk, bk, Wv, bv);

    static bool attr_set = false;
    if (!attr_set) {
        cudaFuncSetAttribute(attn_mma,
                             cudaFuncAttributeMaxDynamicSharedMemorySize, SMEM_ATTN);
        attr_set = true;
    }
    dim3 grid2(N / 128, HEAD, B);
    attn_mma<<<grid2, 256, SMEM_ATTN>>>(x, rel_h, rel_w, out);
}

// round 6
// speedup vs baseline: 3.4603x; 1.3504x over previous
#include <cuda_runtime.h>
#include <cstdint>

// Problem constants
constexpr int B    = 16;
constexpr int C    = 512;
constexpr int HEAD = 8;
constexpr int D    = 64;     // C / HEAD
constexpr int N    = 1024;   // 32*32
constexpr int IMG  = 32;

// Scratch (no allocations allowed -> __device__ globals)
__device__ float g_q[B * C * N];
__device__ float g_k[B * C * N];
__device__ float g_v[B * C * N];

// ---------------------------------------------------------------------------
// Helpers
// ---------------------------------------------------------------------------
__device__ __forceinline__ uint32_t f2tf(float f) {
    uint32_t u;
    asm("cvt.rna.tf32.f32 %0, %1;" : "=r"(u) : "f"(f));
    return u;
}

__device__ __forceinline__ void mma_tf32(float* c,
                                         uint32_t a0, uint32_t a1, uint32_t a2, uint32_t a3,
                                         uint32_t b0, uint32_t b1) {
    asm volatile(
        "mma.sync.aligned.m16n8k8.row.col.f32.tf32.tf32.f32 "
        "{%0,%1,%2,%3}, {%4,%5,%6,%7}, {%8,%9}, {%0,%1,%2,%3};"
        : "+f"(c[0]), "+f"(c[1]), "+f"(c[2]), "+f"(c[3])
        : "r"(a0), "r"(a1), "r"(a2), "r"(a3), "r"(b0), "r"(b1));
}

__device__ __forceinline__ void cpa16(uint32_t dst, const float* src) {
    asm volatile("cp.async.cg.shared.global [%0], [%1], 16;"
                 :: "r"(dst), "l"(src));
}
__device__ __forceinline__ void cpa_commit() {
    asm volatile("cp.async.commit_group;");
}
template <int NWAIT>
__device__ __forceinline__ void cpa_wait() {
    asm volatile("cp.async.wait_group %0;" :: "n"(NWAIT));
}

// ---------------------------------------------------------------------------
// Kernel 1: QKV projection, double-buffered cp.async, conflict-free frags.
// out[b,o,n] = sum_c W[o,c] x[b,c,n] + bias[o]
// Block tile 128(o) x 128(n), BK=32, 8 warps each 32x64.
// Ws layout [o][c] stride 36 (direct cp.async copy of W rows).
// Xs layout [c][n] stride 136.
// ---------------------------------------------------------------------------
constexpr int QW_S     = 36;
constexpr int QX_S     = 136;
constexpr int QW_WORDS = 128 * QW_S;              // 4608
constexpr int QBUF     = QW_WORDS + 32 * QX_S;    // 4608 + 4352 = 8960
constexpr int SMEM_QKV = 2 * QBUF * 4;            // 71680 B

__global__ __launch_bounds__(256) void qkv_mma(
    const float* __restrict__ x,
    const float* __restrict__ Wq, const float* __restrict__ bq,
    const float* __restrict__ Wk, const float* __restrict__ bk,
    const float* __restrict__ Wv, const float* __restrict__ bv)
{
    extern __shared__ uint32_t qsm[];
    const uint32_t sbase = (uint32_t)__cvta_generic_to_shared(qsm);

    const int bz = blockIdx.z;
    const int b = bz % B;
    const int which = bz / B;
    const float* Wm   = (which == 0) ? Wq : (which == 1) ? Wk : Wv;
    const float* bias = (which == 0) ? bq : (which == 1) ? bk : bv;
    float* outp       = (which == 0) ? g_q : (which == 1) ? g_k : g_v;

    const int o0 = blockIdx.y * 128;
    const int n0 = blockIdx.x * 128;
    const int t = threadIdx.x;
    const int lane = t & 31, wid = t >> 5;
    const int g = lane >> 2, t4 = lane & 3;
    const int wm = (wid >> 1) * 32;
    const int wn = (wid & 1) * 64;

    float acc[2][8][4] = {};

    // issue one (W,X) tile pair
    auto issue = [&](int c0, int bufw) {
        {
            int colw = (t & 7) * 4;
            int o = t >> 3;
            #pragma unroll
            for (int r = 0; r < 4; r++)
                cpa16(sbase + (bufw + (o + r * 32) * QW_S + colw) * 4,
                      Wm + (size_t)(o0 + o + r * 32) * C + c0 + colw);
        }
        {
            int colx = (t & 31) * 4;
            int c = t >> 5;
            #pragma unroll
            for (int r = 0; r < 4; r++)
                cpa16(sbase + (bufw + QW_WORDS + (c + r * 8) * QX_S + colx) * 4,
                      x + ((size_t)b * C + c0 + c + r * 8) * N + n0 + colx);
        }
    };

    issue(0, 0);
    cpa_commit();

    for (int ti = 0; ti < 16; ti++) {
        const int bufw = (ti & 1) * QBUF;
        if (ti < 15) {
            issue((ti + 1) * 32, ((ti + 1) & 1) * QBUF);
            cpa_commit();
            cpa_wait<1>();
        } else {
            cpa_wait<0>();
        }
        __syncthreads();

        // in-place cvt to tf32 (RNA)
        for (int w = t * 4; w < QBUF; w += 1024) {
            uint4 v = *(uint4*)&qsm[bufw + w];
            v.x = f2tf(__uint_as_float(v.x));
            v.y = f2tf(__uint_as_float(v.y));
            v.z = f2tf(__uint_as_float(v.z));
            v.w = f2tf(__uint_as_float(v.w));
            *(uint4*)&qsm[bufw + w] = v;
        }
        __syncthreads();

        const uint32_t* Ws = qsm + bufw;              // [o][c] stride 36
        const uint32_t* Xs = qsm + bufw + QW_WORDS;   // [c][n] stride 136

        #pragma unroll
        for (int kk = 0; kk < 4; kk++) {
            int k0 = kk * 8;
            uint32_t a[2][4];
            #pragma unroll
            for (int i = 0; i < 2; i++) {
                int m = wm + i * 16;
                a[i][0] = Ws[(m + g) * QW_S + k0 + t4];
                a[i][1] = Ws[(m + g + 8) * QW_S + k0 + t4];
                a[i][2] = Ws[(m + g) * QW_S + k0 + t4 + 4];
                a[i][3] = Ws[(m + g + 8) * QW_S + k0 + t4 + 4];
            }
            #pragma unroll
            for (int jf = 0; jf < 8; jf++) {
                uint32_t b0 = Xs[(k0 + t4) * QX_S + wn + jf * 8 + g];
                uint32_t b1 = Xs[(k0 + t4 + 4) * QX_S + wn + jf * 8 + g];
                mma_tf32(acc[0][jf], a[0][0], a[0][1], a[0][2], a[0][3], b0, b1);
                mma_tf32(acc[1][jf], a[1][0], a[1][1], a[1][2], a[1][3], b0, b1);
            }
        }
        __syncthreads();
    }

    // Epilogue: add bias, store fp32
    #pragma unroll
    for (int i = 0; i < 2; i++) {
        int o_lo = o0 + wm + i * 16 + g;
        float b_lo = bias[o_lo], b_hi = bias[o_lo + 8];
        #pragma unroll
        for (int jf = 0; jf < 8; jf++) {
            int n = n0 + wn + jf * 8 + 2 * t4;
            float2 v0 = {acc[i][jf][0] + b_lo, acc[i][jf][1] + b_lo};
            float2 v1 = {acc[i][jf][2] + b_hi, acc[i][jf][3] + b_hi};
            *(float2*)&outp[((size_t)b * C + o_lo) * N + n] = v0;
            *(float2*)&outp[((size_t)b * C + o_lo + 8) * N + n] = v1;
        }
    }
}

// ---------------------------------------------------------------------------
// Kernel 2: flash attention via tf32 mma.
// E[i,j] = sum_{d'<128} A[d',i] * Bm[d',j],  A=[q;pos], Bm=[k;q]
// A-frags resident in registers; Bs/Vs double-buffered via cp.async.
// Vst kept in native [dd][j] layout (col-major B-frag for PV).
// grid: (N/128, HEAD, B), 256 threads, 8 warps x 16 query rows.
// ---------------------------------------------------------------------------
constexpr int SA = 136;
constexpr int SB = 72;
constexpr int SV = 68;
constexpr int BS_WORDS  = 128 * SB;               // 9216
constexpr int BUF_WORDS = BS_WORDS + 64 * SV;     // 13568
constexpr int AS_OFF    = 2 * BUF_WORDS;          // 27136
constexpr int OS_STRIDE = 69;
constexpr int SMEM_ATTN = (AS_OFF + 128 * SA) * 4;  // 178176 B

__global__ __launch_bounds__(256) void attn_mma(
    const float* __restrict__ x,
    const float* __restrict__ rel_h,
    const float* __restrict__ rel_w,
    float* __restrict__ out)
{
    extern __shared__ uint32_t smem[];
    const uint32_t sbase = (uint32_t)__cvta_generic_to_shared(smem);

    const int i0 = blockIdx.x * 128;
    const int h  = blockIdx.y;
    const int b  = blockIdx.z;
    const int t  = threadIdx.x;
    const int lane = t & 31, wid = t >> 5;
    const int g = lane >> 2, t4 = lane & 3;
    const int iw = wid * 16;

    const float* qb = g_q + (size_t)(b * C + h * D) * N;
    const float* kb = g_k + (size_t)(b * C + h * D) * N;
    const float* vb = g_v + (size_t)(b * C + h * D) * N;

    // issue one j-tile: Bs rows [0,64)=k, [64,128)=q; Vst [dd][j]
    auto issue = [&](int j0, int bufw) {
        int col = (t & 15) * 4;
        int dd  = t >> 4;
        #pragma unroll
        for (int r = 0; r < 4; r++) {
            int row = dd + r * 16;
            cpa16(sbase + (bufw + row * SB + col) * 4,
                  kb + (size_t)row * N + j0 + col);
            cpa16(sbase + (bufw + (64 + row) * SB + col) * 4,
                  qb + (size_t)row * N + j0 + col);
            cpa16(sbase + (bufw + BS_WORDS + row * SV + col) * 4,
                  vb + (size_t)row * N + j0 + col);
        }
    };

    issue(0, 0);
    cpa_commit();

    // ---- Stage A-side (q;pos) into As with explicit RNA cvt
    {
        int col = (t & 31) * 4;
        int hh = col & 31;
        int ww = (i0 + col) >> 5;
        #pragma unroll
        for (int r = 0; r < 8; r++) {
            int dd = (t >> 5) + r * 8;
            float4 q4 = *(const float4*)&qb[(size_t)dd * N + i0 + col];
            *(uint4*)&smem[AS_OFF + dd * SA + col] =
                make_uint4(f2tf(q4.x), f2tf(q4.y), f2tf(q4.z), f2tf(q4.w));
            const float* rh = &rel_h[(h * D + dd) * IMG + hh];
            float rw = rel_w[(h * D + dd) * IMG + ww];
            *(uint4*)&smem[AS_OFF + (64 + dd) * SA + col] =
                make_uint4(f2tf(rh[0] + rw), f2tf(rh[1] + rw),
                           f2tf(rh[2] + rw), f2tf(rh[3] + rw));
        }
    }
    __syncthreads();

    // ---- A-fragments to registers (invariant across j-tiles)
    uint32_t afr[16][4];
    #pragma unroll
    for (int kk = 0; kk < 16; kk++) {
        int k0 = kk * 8;
        afr[kk][0] = smem[AS_OFF + (k0 + t4) * SA + iw + g];
        afr[kk][1] = smem[AS_OFF + (k0 + t4) * SA + iw + g + 8];
        afr[kk][2] = smem[AS_OFF + (k0 + t4 + 4) * SA + iw + g];
        afr[kk][3] = smem[AS_OFF + (k0 + t4 + 4) * SA + iw + g + 8];
    }

    float m0 = -1e30f, m1 = -1e30f, l0 = 0.f, l1 = 0.f;
    float o_acc[8][4] = {};

    for (int ti = 0; ti < 16; ti++) {
        const int bufw = (ti & 1) * BUF_WORDS;
        if (ti < 15) {
            issue((ti + 1) * 64, ((ti + 1) & 1) * BUF_WORDS);
            cpa_commit();
            cpa_wait<1>();
        } else {
            cpa_wait<0>();
        }
        __syncthreads();

        // in-place cvt to tf32 (RNA) of the whole buffer
        for (int w = t * 4; w < BUF_WORDS; w += 1024) {
            uint4 v = *(uint4*)&smem[bufw + w];
            v.x = f2tf(__uint_as_float(v.x));
            v.y = f2tf(__uint_as_float(v.y));
            v.z = f2tf(__uint_as_float(v.z));
            v.w = f2tf(__uint_as_float(v.w));
            *(uint4*)&smem[bufw + w] = v;
        }
        __syncthreads();

        const uint32_t* Bb = smem + bufw;              // [k][j] stride 72
        const uint32_t* Vb = smem + bufw + BS_WORDS;   // [dd][j] stride 68

        // ---- S = A^T B  (warp tile 16 x 64), inner dim 128
        float s[8][4] = {};
        #pragma unroll
        for (int kk = 0; kk < 16; kk++) {
            int k0 = kk * 8;
            #pragma unroll
            for (int jf = 0; jf < 8; jf++) {
                uint32_t b0 = Bb[(k0 + t4) * SB + jf * 8 + g];
                uint32_t b1 = Bb[(k0 + t4 + 4) * SB + jf * 8 + g];
                mma_tf32(s[jf], afr[kk][0], afr[kk][1], afr[kk][2], afr[kk][3],
                         b0, b1);
            }
        }

        // ---- Online softmax (warp-local; rows g and g+8)
        float mx0 = -1e30f, mx1 = -1e30f;
        #pragma unroll
        for (int jf = 0; jf < 8; jf++) {
            mx0 = fmaxf(mx0, fmaxf(s[jf][0], s[jf][1]));
            mx1 = fmaxf(mx1, fmaxf(s[jf][2], s[jf][3]));
        }
        #pragma unroll
        for (int off = 1; off <= 2; off <<= 1) {
            mx0 = fmaxf(mx0, __shfl_xor_sync(0xffffffffu, mx0, off));
            mx1 = fmaxf(mx1, __shfl_xor_sync(0xffffffffu, mx1, off));
        }
        float mn0 = fmaxf(m0, mx0), mn1 = fmaxf(m1, mx1);
        float sc0 = __expf(m0 - mn0), sc1 = __expf(m1 - mn1);
        float ls0 = 0.f, ls1 = 0.f;
        #pragma unroll
        for (int jf = 0; jf < 8; jf++) {
            float p;
            p = __uint_as_float(f2tf(__expf(s[jf][0] - mn0))); s[jf][0] = p; ls0 += p;
            p = __uint_as_float(f2tf(__expf(s[jf][1] - mn0))); s[jf][1] = p; ls0 += p;
            p = __uint_as_float(f2tf(__expf(s[jf][2] - mn1))); s[jf][2] = p; ls1 += p;
            p = __uint_as_float(f2tf(__expf(s[jf][3] - mn1))); s[jf][3] = p; ls1 += p;
        }
        #pragma unroll
        for (int off = 1; off <= 2; off <<= 1) {
            ls0 += __shfl_xor_sync(0xffffffffu, ls0, off);
            ls1 += __shfl_xor_sync(0xffffffffu, ls1, off);
        }
        l0 = l0 * sc0 + ls0;
        l1 = l1 * sc1 + ls1;
        m0 = mn0; m1 = mn1;
        #pragma unroll
        for (int df = 0; df < 8; df++) {
            o_acc[df][0] *= sc0; o_acc[df][1] *= sc0;
            o_acc[df][2] *= sc1; o_acc[df][3] *= sc1;
        }

        // ---- PV: O[m,dd] += P[m,j] V[dd,j].  P->A-frag via shfl, V col-major.
        const int srcb = lane & ~3;
        const int s_lo = srcb + (t4 >> 1);
        const bool odd = (t4 & 1);
        #pragma unroll
        for (int jq = 0; jq < 8; jq++) {
            uint32_t c0 = __float_as_uint(s[jq][0]);
            uint32_t c1 = __float_as_uint(s[jq][1]);
            uint32_t c2 = __float_as_uint(s[jq][2]);
            uint32_t c3 = __float_as_uint(s[jq][3]);
            uint32_t e, o_;
            e  = __shfl_sync(0xffffffffu, c0, s_lo);
            o_ = __shfl_sync(0xffffffffu, c1, s_lo);
            uint32_t a0 = odd ? o_ : e;
            e  = __shfl_sync(0xffffffffu, c0, s_lo + 2);
            o_ = __shfl_sync(0xffffffffu, c1, s_lo + 2);
            uint32_t a2 = odd ? o_ : e;
            e  = __shfl_sync(0xffffffffu, c2, s_lo);
            o_ = __shfl_sync(0xffffffffu, c3, s_lo);
            uint32_t a1 = odd ? o_ : e;
            e  = __shfl_sync(0xffffffffu, c2, s_lo + 2);
            o_ = __shfl_sync(0xffffffffu, c3, s_lo + 2);
            uint32_t a3 = odd ? o_ : e;
            #pragma unroll
            for (int df = 0; df < 8; df++) {
                uint32_t b0 = Vb[(df * 8 + g) * SV + jq * 8 + t4];
                uint32_t b1 = Vb[(df * 8 + g) * SV + jq * 8 + t4 + 4];
                mma_tf32(o_acc[df], a0, a1, a2, a3, b0, b1);
            }
        }
        __syncthreads();
    }

    // ---- Normalize, stage to smem (reuse As region), coalesced +x write
    float* Os = (float*)(smem + AS_OFF);
    float inv0 = 1.f / l0, inv1 = 1.f / l1;
    #pragma unroll
    for (int df = 0; df < 8; df++) {
        int dd = df * 8 + 2 * t4;
        Os[(iw + g) * OS_STRIDE + dd]         = o_acc[df][0] * inv0;
        Os[(iw + g) * OS_STRIDE + dd + 1]     = o_acc[df][1] * inv0;
        Os[(iw + g + 8) * OS_STRIDE + dd]     = o_acc[df][2] * inv1;
        Os[(iw + g + 8) * OS_STRIDE + dd + 1] = o_acc[df][3] * inv1;
    }
    __syncthreads();

    for (int idx = t; idx < 128 * 64; idx += 256) {
        int dd = idx >> 7, mm = idx & 127;
        size_t gi = ((size_t)(b * C) + h * D + dd) * N + i0 + mm;
        out[gi] = Os[mm * OS_STRIDE + dd] + x[gi];
    }
}

// ---------------------------------------------------------------------------
extern "C" void kernel_launch(void* const* d_in, const int* in_sizes, int n_in,
                              void* d_out, int out_size)
{
    const float* x     = (const float*)d_in[0];
    const float* Wq    = (const float*)d_in[1];
    const float* bq    = (const float*)d_in[2];
    const float* Wk    = (const float*)d_in[3];
    const float* bk    = (const float*)d_in[4];
    const float* Wv    = (const float*)d_in[5];
    const float* bv    = (const float*)d_in[6];
    const float* rel_h = (const float*)d_in[7];
    const float* rel_w = (const float*)d_in[8];
    // d_in[9] (reg_qk) and d_in[10] (reg_v) are dead: that group is dropped
    // by out[:, :head].
    float* out = (float*)d_out;

    static bool attr_set = false;
    if (!attr_set) {
        cudaFuncSetAttribute(qkv_mma,
                             cudaFuncAttributeMaxDynamicSharedMemorySize, SMEM_QKV);
        cudaFuncSetAttribute(attn_mma,
                             cudaFuncAttributeMaxDynamicSharedMemorySize, SMEM_ATTN);
        attr_set = true;
    }

    dim3 grid1(N / 128, C / 128, 3 * B);
    qkv_mma<<<grid1, 256, SMEM_QKV>>>(x, Wq, bq, Wk, bk, Wv, bv);

    dim3 grid2(N / 128, HEAD, B);
    attn_mma<<<grid2, 256, SMEM_ATTN>>>(x, rel_h, rel_w, out);
}

// round 7
// speedup vs baseline: 5.4942x; 1.5878x over previous
#include <cuda_runtime.h>
#include <cuda_fp16.h>
#include <cstdint>

// Problem constants
constexpr int B    = 16;
constexpr int C    = 512;
constexpr int HEAD = 8;
constexpr int D    = 64;     // C / HEAD
constexpr int N    = 1024;   // 32*32
constexpr int IMG  = 32;

// Scratch (no allocations allowed -> __device__ globals)
// Transposed half layouts produced by the QKV epilogue:
//   g_qT/g_kT: [b][h][n][d]  (d contiguous)  -> fp16 frag k-pairs direct
//   g_vh:      [b][h][d][n]  (n contiguous)  -> PV B-frag k-pairs direct
__device__ __half g_qT[B * HEAD * N * D];
__device__ __half g_kT[B * HEAD * N * D];
__device__ __half g_vh[B * HEAD * D * N];

// ---------------------------------------------------------------------------
// Helpers
// ---------------------------------------------------------------------------
__device__ __forceinline__ uint32_t f2tf(float f) {
    uint32_t u;
    asm("cvt.rna.tf32.f32 %0, %1;" : "=r"(u) : "f"(f));
    return u;
}

__device__ __forceinline__ void mma_tf32(float* c,
                                         uint32_t a0, uint32_t a1, uint32_t a2, uint32_t a3,
                                         uint32_t b0, uint32_t b1) {
    asm volatile(
        "mma.sync.aligned.m16n8k8.row.col.f32.tf32.tf32.f32 "
        "{%0,%1,%2,%3}, {%4,%5,%6,%7}, {%8,%9}, {%0,%1,%2,%3};"
        : "+f"(c[0]), "+f"(c[1]), "+f"(c[2]), "+f"(c[3])
        : "r"(a0), "r"(a1), "r"(a2), "r"(a3), "r"(b0), "r"(b1));
}

__device__ __forceinline__ void mma_f16(float* c,
                                        uint32_t a0, uint32_t a1, uint32_t a2, uint32_t a3,
                                        uint32_t b0, uint32_t b1) {
    asm volatile(
        "mma.sync.aligned.m16n8k16.row.col.f32.f16.f16.f32 "
        "{%0,%1,%2,%3}, {%4,%5,%6,%7}, {%8,%9}, {%0,%1,%2,%3};"
        : "+f"(c[0]), "+f"(c[1]), "+f"(c[2]), "+f"(c[3])
        : "r"(a0), "r"(a1), "r"(a2), "r"(a3), "r"(b0), "r"(b1));
}

// pack two floats as half2 bits: lo = first (lower k index), hi = second
__device__ __forceinline__ uint32_t pack2h(float lo, float hi) {
    uint32_t r;
    asm("cvt.rn.f16x2.f32 %0, %1, %2;" : "=r"(r) : "f"(hi), "f"(lo));
    return r;
}

__device__ __forceinline__ void cpa16(uint32_t dst, const void* src) {
    asm volatile("cp.async.cg.shared.global [%0], [%1], 16;"
                 :: "r"(dst), "l"(src));
}
__device__ __forceinline__ void cpa_commit() {
    asm volatile("cp.async.commit_group;");
}
template <int NWAIT>
__device__ __forceinline__ void cpa_wait() {
    asm volatile("cp.async.wait_group %0;" :: "n"(NWAIT));
}

// ---------------------------------------------------------------------------
// Kernel 1: QKV projection (tf32 mainloop, unchanged), NEW epilogue that
// emits half outputs in the layouts attention wants:
//   which 0 (q) -> g_qT [n][d], which 1 (k) -> g_kT [n][d],
//   which 2 (v) -> g_vh [d][n]
// ---------------------------------------------------------------------------
constexpr int QW_S     = 36;
constexpr int QX_S     = 136;
constexpr int QW_WORDS = 128 * QW_S;              // 4608
constexpr int QBUF     = QW_WORDS + 32 * QX_S;    // 8960
constexpr int SMEM_QKV = 2 * QBUF * 4;            // 71680 B

__global__ __launch_bounds__(256) void qkv_mma(
    const float* __restrict__ x,
    const float* __restrict__ Wq, const float* __restrict__ bq,
    const float* __restrict__ Wk, const float* __restrict__ bk,
    const float* __restrict__ Wv, const float* __restrict__ bv)
{
    extern __shared__ uint32_t qsm[];
    const uint32_t sbase = (uint32_t)__cvta_generic_to_shared(qsm);

    const int bz = blockIdx.z;
    const int b = bz % B;
    const int which = bz / B;
    const float* Wm   = (which == 0) ? Wq : (which == 1) ? Wk : Wv;
    const float* bias = (which == 0) ? bq : (which == 1) ? bk : bv;

    const int o0 = blockIdx.y * 128;
    const int n0 = blockIdx.x * 128;
    const int t = threadIdx.x;
    const int lane = t & 31, wid = t >> 5;
    const int g = lane >> 2, t4 = lane & 3;
    const int wm = (wid >> 1) * 32;
    const int wn = (wid & 1) * 64;

    float acc[2][8][4] = {};

    auto issue = [&](int c0, int bufw) {
        {
            int colw = (t & 7) * 4;
            int o = t >> 3;
            #pragma unroll
            for (int r = 0; r < 4; r++)
                cpa16(sbase + (bufw + (o + r * 32) * QW_S + colw) * 4,
                      Wm + (size_t)(o0 + o + r * 32) * C + c0 + colw);
        }
        {
            int colx = (t & 31) * 4;
            int c = t >> 5;
            #pragma unroll
            for (int r = 0; r < 4; r++)
                cpa16(sbase + (bufw + QW_WORDS + (c + r * 8) * QX_S + colx) * 4,
                      x + ((size_t)b * C + c0 + c + r * 8) * N + n0 + colx);
        }
    };

    issue(0, 0);
    cpa_commit();

    for (int ti = 0; ti < 16; ti++) {
        const int bufw = (ti & 1) * QBUF;
        if (ti < 15) {
            issue((ti + 1) * 32, ((ti + 1) & 1) * QBUF);
            cpa_commit();
            cpa_wait<1>();
        } else {
            cpa_wait<0>();
        }
        __syncthreads();

        // in-place cvt to tf32 (RNA)
        for (int w = t * 4; w < QBUF; w += 1024) {
            uint4 v = *(uint4*)&qsm[bufw + w];
            v.x = f2tf(__uint_as_float(v.x));
            v.y = f2tf(__uint_as_float(v.y));
            v.z = f2tf(__uint_as_float(v.z));
            v.w = f2tf(__uint_as_float(v.w));
            *(uint4*)&qsm[bufw + w] = v;
        }
        __syncthreads();

        const uint32_t* Ws = qsm + bufw;              // [o][c] stride 36
        const uint32_t* Xs = qsm + bufw + QW_WORDS;   // [c][n] stride 136

        #pragma unroll
        for (int kk = 0; kk < 4; kk++) {
            int k0 = kk * 8;
            uint32_t a[2][4];
            #pragma unroll
            for (int i = 0; i < 2; i++) {
                int m = wm + i * 16;
                a[i][0] = Ws[(m + g) * QW_S + k0 + t4];
                a[i][1] = Ws[(m + g + 8) * QW_S + k0 + t4];
                a[i][2] = Ws[(m + g) * QW_S + k0 + t4 + 4];
                a[i][3] = Ws[(m + g + 8) * QW_S + k0 + t4 + 4];
            }
            #pragma unroll
            for (int jf = 0; jf < 8; jf++) {
                uint32_t b0 = Xs[(k0 + t4) * QX_S + wn + jf * 8 + g];
                uint32_t b1 = Xs[(k0 + t4 + 4) * QX_S + wn + jf * 8 + g];
                mma_tf32(acc[0][jf], a[0][0], a[0][1], a[0][2], a[0][3], b0, b1);
                mma_tf32(acc[1][jf], a[1][0], a[1][1], a[1][2], a[1][3], b0, b1);
            }
        }
        __syncthreads();
    }

    // Epilogue: add bias, convert to half, store transposed (q,k) / natural (v)
    #pragma unroll
    for (int i = 0; i < 2; i++) {
        const int r0 = o0 + wm + i * 16 + g;     // global o row (and r0+8)
        const int h0 = r0 >> 6;                  // head (r0, r0+8 same head)
        const int d0 = r0 & 63;                  // d within head
        const float b_lo = bias[r0], b_hi = bias[r0 + 8];
        #pragma unroll
        for (int jf = 0; jf < 8; jf++) {
            const int n = n0 + wn + jf * 8 + 2 * t4;
            float v00 = acc[i][jf][0] + b_lo, v01 = acc[i][jf][1] + b_lo;
            float v10 = acc[i][jf][2] + b_hi, v11 = acc[i][jf][3] + b_hi;
            if (which == 2) {
                __half* dst = g_vh + ((size_t)(b * HEAD + h0) * D) * N;
                *(uint32_t*)&dst[(size_t)d0 * N + n]       = pack2h(v00, v01);
                *(uint32_t*)&dst[(size_t)(d0 + 8) * N + n] = pack2h(v10, v11);
            } else {
                __half* dst = (which ? g_kT : g_qT)
                              + (size_t)(b * HEAD + h0) * N * D;
                dst[(size_t)n * D + d0]           = __float2half_rn(v00);
                dst[(size_t)(n + 1) * D + d0]     = __float2half_rn(v01);
                dst[(size_t)n * D + d0 + 8]       = __float2half_rn(v10);
                dst[(size_t)(n + 1) * D + d0 + 8] = __float2half_rn(v11);
            }
        }
    }
}

// ---------------------------------------------------------------------------
// Kernel 2: flash attention via fp16 m16n8k16 mma.
// E[i,j] = sum_{d'<128} A[i,d'] B[d',j],  A=[q;pos] (regs), B=[k;q] (smem).
// smem per j-tile: KQ rows j (64 x 256B = [kT(j)|qT(j)]) + V rows d (64x128B).
// Double-buffered cp.async; no cvt pass (data already half).
// grid: (N/128, HEAD, B), 256 threads, 8 warps x 16 query rows.
// ---------------------------------------------------------------------------
constexpr int SKQ = 68;                        // words per KQ row (64 + 4 pad)
constexpr int SVW = 36;                        // words per V row  (32 + 4 pad)
constexpr int KQ_WORDS  = 64 * SKQ;            // 4352
constexpr int BUF_WORDS = KQ_WORDS + 64 * SVW; // 6656
constexpr int OS_STRIDE = 69;
constexpr int SMEM_ATTN = 2 * BUF_WORDS * 4;   // 53248 B (Os aliases buffers)

__global__ __launch_bounds__(256) void attn_f16(
    const float* __restrict__ x,
    const float* __restrict__ rel_h,
    const float* __restrict__ rel_w,
    float* __restrict__ out)
{
    extern __shared__ uint32_t smem[];
    const uint32_t sbase = (uint32_t)__cvta_generic_to_shared(smem);

    const int i0 = blockIdx.x * 128;
    const int h  = blockIdx.y;
    const int b  = blockIdx.z;
    const int t  = threadIdx.x;
    const int lane = t & 31, wid = t >> 5;
    const int g = lane >> 2, t4 = lane & 3;
    const int iw = wid * 16;

    const __half* qT = g_qT + (size_t)(b * HEAD + h) * N * D;
    const __half* kT = g_kT + (size_t)(b * HEAD + h) * N * D;
    const __half* vh = g_vh + (size_t)(b * HEAD + h) * D * N;

    // issue one j-tile: KQ rows j = [kT(j) | qT(j)] (256B), V rows d (128B)
    const int irow = t >> 2, iseg = t & 3;
    auto issue = [&](int j0, int bufw) {
        #pragma unroll
        for (int cc = 0; cc < 4; cc++) {
            int c = iseg + cc * 4;   // 16B chunk 0..15 within the 256B row
            const __half* src = (c < 8)
                ? kT + (size_t)(j0 + irow) * D + c * 8
                : qT + (size_t)(j0 + irow) * D + (c - 8) * 8;
            cpa16(sbase + (bufw + irow * SKQ + c * 4) * 4, src);
        }
        #pragma unroll
        for (int cc = 0; cc < 2; cc++) {
            int c = iseg + cc * 4;   // 16B chunk 0..7 within the 128B row
            cpa16(sbase + (bufw + KQ_WORDS + irow * SVW + c * 4) * 4,
                  vh + (size_t)irow * N + j0 + c * 8);
        }
    };

    issue(0, 0);
    cpa_commit();

    // ---- Stationary A-fragments (q;pos), half2 pairs along d'
    uint32_t afr[8][4];
    {
        const int r0 = i0 + iw + g;       // query rows r0 and r0+8
        const int r1 = r0 + 8;
        #pragma unroll
        for (int kc = 0; kc < 4; kc++) {  // q-part: d' = kc*16 + ...
            int dlo = kc * 16 + 2 * t4, dhi = dlo + 8;
            afr[kc][0] = *(const uint32_t*)&qT[(size_t)r0 * D + dlo];
            afr[kc][1] = *(const uint32_t*)&qT[(size_t)r1 * D + dlo];
            afr[kc][2] = *(const uint32_t*)&qT[(size_t)r0 * D + dhi];
            afr[kc][3] = *(const uint32_t*)&qT[(size_t)r1 * D + dhi];
        }
        auto posv = [&](int d, int i) {
            return rel_h[(h * D + d) * IMG + (i & 31)]
                 + rel_w[(h * D + d) * IMG + (i >> 5)];
        };
        #pragma unroll
        for (int kc = 0; kc < 4; kc++) {  // pos-part: d = kc*16 + ...
            int dlo = kc * 16 + 2 * t4, dhi = dlo + 8;
            afr[4 + kc][0] = pack2h(posv(dlo, r0), posv(dlo + 1, r0));
            afr[4 + kc][1] = pack2h(posv(dlo, r1), posv(dlo + 1, r1));
            afr[4 + kc][2] = pack2h(posv(dhi, r0), posv(dhi + 1, r0));
            afr[4 + kc][3] = pack2h(posv(dhi, r1), posv(dhi + 1, r1));
        }
    }

    float m0 = -1e30f, m1 = -1e30f, l0 = 0.f, l1 = 0.f;
    float o_acc[8][4] = {};

    for (int ti = 0; ti < 16; ti++) {
        const int bufw = (ti & 1) * BUF_WORDS;
        if (ti < 15) {
            issue((ti + 1) * 64, ((ti + 1) & 1) * BUF_WORDS);
            cpa_commit();
            cpa_wait<1>();
        } else {
            cpa_wait<0>();
        }
        __syncthreads();

        const uint32_t* Bb = smem + bufw;              // KQ [j][d'-pair w]
        const uint32_t* Vb = smem + bufw + KQ_WORDS;   // V  [d][j-pair w]

        // ---- S = A B (warp tile 16 x 64), k = 128 in 8 chunks
        float s[8][4] = {};
        #pragma unroll
        for (int kc = 0; kc < 8; kc++) {
            #pragma unroll
            for (int jf = 0; jf < 8; jf++) {
                uint32_t b0 = Bb[(jf * 8 + g) * SKQ + kc * 8 + t4];
                uint32_t b1 = Bb[(jf * 8 + g) * SKQ + kc * 8 + 4 + t4];
                mma_f16(s[jf], afr[kc][0], afr[kc][1], afr[kc][2], afr[kc][3],
                        b0, b1);
            }
        }

        // ---- Online softmax (warp-local; rows g and g+8)
        float mx0 = -1e30f, mx1 = -1e30f;
        #pragma unroll
        for (int jf = 0; jf < 8; jf++) {
            mx0 = fmaxf(mx0, fmaxf(s[jf][0], s[jf][1]));
            mx1 = fmaxf(mx1, fmaxf(s[jf][2], s[jf][3]));
        }
        #pragma unroll
        for (int off = 1; off <= 2; off <<= 1) {
            mx0 = fmaxf(mx0, __shfl_xor_sync(0xffffffffu, mx0, off));
            mx1 = fmaxf(mx1, __shfl_xor_sync(0xffffffffu, mx1, off));
        }
        float mn0 = fmaxf(m0, mx0), mn1 = fmaxf(m1, mx1);
        float sc0 = __expf(m0 - mn0), sc1 = __expf(m1 - mn1);
        float ls0 = 0.f, ls1 = 0.f;
        uint32_t ph[8][2];   // P as half2 A-frag pairs (row g / row g+8)
        #pragma unroll
        for (int jf = 0; jf < 8; jf++) {
            float p0 = __expf(s[jf][0] - mn0);
            float p1 = __expf(s[jf][1] - mn0);
            float p2 = __expf(s[jf][2] - mn1);
            float p3 = __expf(s[jf][3] - mn1);
            uint32_t lo = pack2h(p0, p1);
            uint32_t hi = pack2h(p2, p3);
            ph[jf][0] = lo; ph[jf][1] = hi;
            // l accumulates the half-rounded P (consistent with PV)
            float2 f0 = __half22float2(*(__half2*)&lo);
            float2 f1 = __half22float2(*(__half2*)&hi);
            ls0 += f0.x + f0.y;
            ls1 += f1.x + f1.y;
        }
        #pragma unroll
        for (int off = 1; off <= 2; off <<= 1) {
            ls0 += __shfl_xor_sync(0xffffffffu, ls0, off);
            ls1 += __shfl_xor_sync(0xffffffffu, ls1, off);
        }
        l0 = l0 * sc0 + ls0;
        l1 = l1 * sc1 + ls1;
        m0 = mn0; m1 = mn1;
        #pragma unroll
        for (int df = 0; df < 8; df++) {
            o_acc[df][0] *= sc0; o_acc[df][1] *= sc0;
            o_acc[df][2] *= sc1; o_acc[df][3] *= sc1;
        }

        // ---- PV: O[i,dd] += P[i,j] V[dd,j]; A-frags are ph pairs directly
        #pragma unroll
        for (int jc = 0; jc < 4; jc++) {
            uint32_t a0 = ph[2 * jc][0],     a1 = ph[2 * jc][1];
            uint32_t a2 = ph[2 * jc + 1][0], a3 = ph[2 * jc + 1][1];
            #pragma unroll
            for (int df = 0; df < 8; df++) {
                uint32_t b0 = Vb[(df * 8 + g) * SVW + jc * 8 + t4];
                uint32_t b1 = Vb[(df * 8 + g) * SVW + jc * 8 + 4 + t4];
                mma_f16(o_acc[df], a0, a1, a2, a3, b0, b1);
            }
        }
        __syncthreads();
    }

    // ---- Normalize, stage to smem (alias buffers), coalesced +x write
    float* Os = (float*)smem;
    float inv0 = 1.f / l0, inv1 = 1.f / l1;
    #pragma unroll
    for (int df = 0; df < 8; df++) {
        int dd = df * 8 + 2 * t4;
        Os[(iw + g) * OS_STRIDE + dd]         = o_acc[df][0] * inv0;
        Os[(iw + g) * OS_STRIDE + dd + 1]     = o_acc[df][1] * inv0;
        Os[(iw + g + 8) * OS_STRIDE + dd]     = o_acc[df][2] * inv1;
        Os[(iw + g + 8) * OS_STRIDE + dd + 1] = o_acc[df][3] * inv1;
    }
    __syncthreads();

    for (int idx = t; idx < 128 * 64; idx += 256) {
        int dd = idx >> 7, mm = idx & 127;
        size_t gi = ((size_t)(b * C) + h * D + dd) * N + i0 + mm;
        out[gi] = Os[mm * OS_STRIDE + dd] + x[gi];
    }
}

// ---------------------------------------------------------------------------
extern "C" void kernel_launch(void* const* d_in, const int* in_sizes, int n_in,
                              void* d_out, int out_size)
{
    const float* x     = (const float*)d_in[0];
    const float* Wq    = (const float*)d_in[1];
    const float* bq    = (const float*)d_in[2];
    const float* Wk    = (const float*)d_in[3];
    const float* bk    = (const float*)d_in[4];
    const float* Wv    = (const float*)d_in[5];
    const float* bv    = (const float*)d_in[6];
    const float* rel_h = (const float*)d_in[7];
    const float* rel_w = (const float*)d_in[8];
    // d_in[9] (reg_qk) and d_in[10] (reg_v) are dead: that group is dropped
    // by out[:, :head].
    float* out = (float*)d_out;

    static bool attr_set = false;
    if (!attr_set) {
        cudaFuncSetAttribute(qkv_mma,
                             cudaFuncAttributeMaxDynamicSharedMemorySize, SMEM_QKV);
        cudaFuncSetAttribute(attn_f16,
                             cudaFuncAttributeMaxDynamicSharedMemorySize, SMEM_ATTN);
        attr_set = true;
    }

    dim3 grid1(N / 128, C / 128, 3 * B);
    qkv_mma<<<grid1, 256, SMEM_QKV>>>(x, Wq, bq, Wk, bk, Wv, bv);

    dim3 grid2(N / 128, HEAD, B);
    attn_f16<<<grid2, 256, SMEM_ATTN>>>(x, rel_h, rel_w, out);
}

// round 9
// speedup vs baseline: 6.6871x; 1.2171x over previous
#include <cuda_runtime.h>
#include <cuda_fp16.h>
#include <cstdint>

// Problem constants
constexpr int B    = 16;
constexpr int C    = 512;
constexpr int HEAD = 8;
constexpr int D    = 64;     // C / HEAD
constexpr int N    = 1024;   // 32*32
constexpr int IMG  = 32;

// Scratch (no allocations allowed -> __device__ globals)
__device__ __half g_qT[B * HEAD * N * D];   // [b][h][n][d]
__device__ __half g_kT[B * HEAD * N * D];   // [b][h][n][d]
__device__ __half g_vh[B * HEAD * D * N];   // [b][h][d][n]
__device__ __half g_Wh[3 * C * C];          // [which][o][c] half
__device__ __half g_xT[B * N * C];          // [b][n][c] half (x transposed)

// ---------------------------------------------------------------------------
// Helpers
// ---------------------------------------------------------------------------
__device__ __forceinline__ void mma_f16(float* c,
                                        uint32_t a0, uint32_t a1, uint32_t a2, uint32_t a3,
                                        uint32_t b0, uint32_t b1) {
    asm volatile(
        "mma.sync.aligned.m16n8k16.row.col.f32.f16.f16.f32 "
        "{%0,%1,%2,%3}, {%4,%5,%6,%7}, {%8,%9}, {%0,%1,%2,%3};"
        : "+f"(c[0]), "+f"(c[1]), "+f"(c[2]), "+f"(c[3])
        : "r"(a0), "r"(a1), "r"(a2), "r"(a3), "r"(b0), "r"(b1));
}

// pack two floats as half2 bits: lo = first (lower index), hi = second
__device__ __forceinline__ uint32_t pack2h(float lo, float hi) {
    uint32_t r;
    asm("cvt.rn.f16x2.f32 %0, %1, %2;" : "=r"(r) : "f"(hi), "f"(lo));
    return r;
}

__device__ __forceinline__ void cpa16(uint32_t dst, const void* src) {
    asm volatile("cp.async.cg.shared.global [%0], [%1], 16;"
                 :: "r"(dst), "l"(src));
}
__device__ __forceinline__ void cpa_commit() {
    asm volatile("cp.async.commit_group;");
}
template <int NWAIT>
__device__ __forceinline__ void cpa_wait() {
    asm volatile("cp.async.wait_group %0;" :: "n"(NWAIT));
}

// ---------------------------------------------------------------------------
// Kernel 0a: W fp32 -> half, straight layout [which][o][c]
// grid: (C*C/1024, 3), 256 threads
// ---------------------------------------------------------------------------
__global__ __launch_bounds__(256) void cvt_w(
    const float* __restrict__ Wq, const float* __restrict__ Wk,
    const float* __restrict__ Wv)
{
    const float* src = (blockIdx.y == 0) ? Wq : (blockIdx.y == 1) ? Wk : Wv;
    __half* dst = g_Wh + (size_t)blockIdx.y * C * C;
    int i = (blockIdx.x * 256 + threadIdx.x) * 4;
    float4 v = *(const float4*)&src[i];
    uint2 o;
    o.x = pack2h(v.x, v.y);
    o.y = pack2h(v.z, v.w);
    *(uint2*)&dst[i] = o;
}

// ---------------------------------------------------------------------------
// Kernel 0b: x [b][c][n] fp32 -> g_xT [b][n][c] half (32x32 smem transpose)
// grid: (N/32, C/32, B), 256 threads (32x8)
// ---------------------------------------------------------------------------
__global__ __launch_bounds__(256) void cvt_xT(const float* __restrict__ x)
{
    __shared__ float tile[32][33];
    const int b = blockIdx.z, c0 = blockIdx.y * 32, n0 = blockIdx.x * 32;
    const int tx = threadIdx.x & 31, ty = threadIdx.x >> 5;
    #pragma unroll
    for (int r = 0; r < 4; r++)
        tile[ty + r * 8][tx] = x[((size_t)b * C + c0 + ty + r * 8) * N + n0 + tx];
    __syncthreads();
    const int n = threadIdx.x >> 3, cs = (threadIdx.x & 7) * 4;
    uint2 o;
    o.x = pack2h(tile[cs][n], tile[cs + 1][n]);
    o.y = pack2h(tile[cs + 2][n], tile[cs + 3][n]);
    *(uint2*)&g_xT[((size_t)b * N + n0 + n) * C + c0 + cs] = o;
}

// ---------------------------------------------------------------------------
// Kernel 1: QKV projection via fp16 m16n8k16 mma.
// out[b,o,n] = sum_c W[o,c] x[b,c,n] + bias[o]
// Block tile 128(o) x 128(n), BK=64, 8 warps each 32x64, double-buffered.
// Ws [o][c] stride-36-word rows; Xs [n][c] stride-36-word rows (from g_xT).
// Epilogue emits half outputs in the layouts attention wants.
// ---------------------------------------------------------------------------
constexpr int QS       = 36;                 // words per row (64 half + pad)
constexpr int QTILE    = 128 * QS;           // 4608 words per operand tile
constexpr int QBUF     = 2 * QTILE;          // W + X = 9216 words
constexpr int SMEM_QKV = 2 * QBUF * 4;       // 73728 B

__global__ __launch_bounds__(256) void qkv_f16(
    const float* __restrict__ bq, const float* __restrict__ bk,
    const float* __restrict__ bv)
{
    extern __shared__ uint32_t qsm[];
    const uint32_t sbase = (uint32_t)__cvta_generic_to_shared(qsm);

    const int bz = blockIdx.z;
    const int b = bz % B;
    const int which = bz / B;
    const __half* Wm  = g_Wh + (size_t)which * C * C;
    const float* bias = (which == 0) ? bq : (which == 1) ? bk : bv;

    const int o0 = blockIdx.y * 128;
    const int n0 = blockIdx.x * 128;
    const int t = threadIdx.x;
    const int lane = t & 31, wid = t >> 5;
    const int g = lane >> 2, t4 = lane & 3;
    const int wm = (wid >> 1) * 32;
    const int wn = (wid & 1) * 64;

    float acc[2][8][4] = {};

    const int irow = t >> 1;
    auto issue = [&](int c0, int bufw) {
        #pragma unroll
        for (int r = 0; r < 4; r++) {
            int seg = (t & 1) * 4 + r;
            cpa16(sbase + (bufw + irow * QS + seg * 4) * 4,
                  Wm + (size_t)(o0 + irow) * C + c0 + seg * 8);
            cpa16(sbase + (bufw + QTILE + irow * QS + seg * 4) * 4,
                  g_xT + ((size_t)b * N + n0 + irow) * C + c0 + seg * 8);
        }
    };

    issue(0, 0);
    cpa_commit();

    for (int ti = 0; ti < 8; ti++) {
        const int bufw = (ti & 1) * QBUF;
        if (ti < 7) {
            issue((ti + 1) * 64, ((ti + 1) & 1) * QBUF);
            cpa_commit();
            cpa_wait<1>();
        } else {
            cpa_wait<0>();
        }
        __syncthreads();

        const uint32_t* Ws = qsm + bufw;           // [o][c-pair w] stride 36
        const uint32_t* Xs = qsm + bufw + QTILE;   // [n][c-pair w] stride 36

        #pragma unroll
        for (int kc = 0; kc < 4; kc++) {
            uint32_t a[2][4];
            #pragma unroll
            for (int i = 0; i < 2; i++) {
                int m = wm + i * 16;
                a[i][0] = Ws[(m + g) * QS + kc * 8 + t4];
                a[i][1] = Ws[(m + g + 8) * QS + kc * 8 + t4];
                a[i][2] = Ws[(m + g) * QS + kc * 8 + 4 + t4];
                a[i][3] = Ws[(m + g + 8) * QS + kc * 8 + 4 + t4];
            }
            #pragma unroll
            for (int jf = 0; jf < 8; jf++) {
                uint32_t b0 = Xs[(wn + jf * 8 + g) * QS + kc * 8 + t4];
                uint32_t b1 = Xs[(wn + jf * 8 + g) * QS + kc * 8 + 4 + t4];
                mma_f16(acc[0][jf], a[0][0], a[0][1], a[0][2], a[0][3], b0, b1);
                mma_f16(acc[1][jf], a[1][0], a[1][1], a[1][2], a[1][3], b0, b1);
            }
        }
        __syncthreads();
    }

    // Epilogue: add bias, convert to half, store transposed (q,k) / natural (v)
    #pragma unroll
    for (int i = 0; i < 2; i++) {
        const int r0 = o0 + wm + i * 16 + g;     // global o row (and r0+8)
        const int h0 = r0 >> 6;                  // head (r0, r0+8 same head)
        const int d0 = r0 & 63;                  // d within head
        const float b_lo = bias[r0], b_hi = bias[r0 + 8];
        #pragma unroll
        for (int jf = 0; jf < 8; jf++) {
            const int n = n0 + wn + jf * 8 + 2 * t4;
            float v00 = acc[i][jf][0] + b_lo, v01 = acc[i][jf][1] + b_lo;
            float v10 = acc[i][jf][2] + b_hi, v11 = acc[i][jf][3] + b_hi;
            if (which == 2) {
                __half* dst = g_vh + ((size_t)(b * HEAD + h0) * D) * N;
                *(uint32_t*)&dst[(size_t)d0 * N + n]       = pack2h(v00, v01);
                *(uint32_t*)&dst[(size_t)(d0 + 8) * N + n] = pack2h(v10, v11);
            } else {
                __half* dst = (which ? g_kT : g_qT)
                              + (size_t)(b * HEAD + h0) * N * D;
                dst[(size_t)n * D + d0]           = __float2half_rn(v00);
                dst[(size_t)(n + 1) * D + d0]     = __float2half_rn(v01);
                dst[(size_t)n * D + d0 + 8]       = __float2half_rn(v10);
                dst[(size_t)(n + 1) * D + d0 + 8] = __float2half_rn(v11);
            }
        }
    }
}

// ---------------------------------------------------------------------------
// Kernel 2: flash attention via fp16 m16n8k16 mma (unchanged from R7).
// ---------------------------------------------------------------------------
constexpr int SKQ = 68;                        // words per KQ row (64 + 4 pad)
constexpr int SVW = 36;                        // words per V row  (32 + 4 pad)
constexpr int KQ_WORDS  = 64 * SKQ;            // 4352
constexpr int BUF_WORDS = KQ_WORDS + 64 * SVW; // 6656
constexpr int OS_STRIDE = 69;
constexpr int SMEM_ATTN = 2 * BUF_WORDS * 4;   // 53248 B (Os aliases buffers)

__global__ __launch_bounds__(256) void attn_f16(
    const float* __restrict__ x,
    const float* __restrict__ rel_h,
    const float* __restrict__ rel_w,
    float* __restrict__ out)
{
    extern __shared__ uint32_t smem[];
    const uint32_t sbase = (uint32_t)__cvta_generic_to_shared(smem);

    const int i0 = blockIdx.x * 128;
    const int h  = blockIdx.y;
    const int b  = blockIdx.z;
    const int t  = threadIdx.x;
    const int lane = t & 31, wid = t >> 5;
    const int g = lane >> 2, t4 = lane & 3;
    const int iw = wid * 16;

    const __half* qT = g_qT + (size_t)(b * HEAD + h) * N * D;
    const __half* kT = g_kT + (size_t)(b * HEAD + h) * N * D;
    const __half* vh = g_vh + (size_t)(b * HEAD + h) * D * N;

    const int irow = t >> 2, iseg = t & 3;
    auto issue = [&](int j0, int bufw) {
        #pragma unroll
        for (int cc = 0; cc < 4; cc++) {
            int c = iseg + cc * 4;
            const __half* src = (c < 8)
                ? kT + (size_t)(j0 + irow) * D + c * 8
                : qT + (size_t)(j0 + irow) * D + (c - 8) * 8;
            cpa16(sbase + (bufw + irow * SKQ + c * 4) * 4, src);
        }
        #pragma unroll
        for (int cc = 0; cc < 2; cc++) {
            int c = iseg + cc * 4;
            cpa16(sbase + (bufw + KQ_WORDS + irow * SVW + c * 4) * 4,
                  vh + (size_t)irow * N + j0 + c * 8);
        }
    };

    issue(0, 0);
    cpa_commit();

    // ---- Stationary A-fragments (q;pos), half2 pairs along d'
    uint32_t afr[8][4];
    {
        const int r0 = i0 + iw + g;
        const int r1 = r0 + 8;
        #pragma unroll
        for (int kc = 0; kc < 4; kc++) {
            int dlo = kc * 16 + 2 * t4, dhi = dlo + 8;
            afr[kc][0] = *(const uint32_t*)&qT[(size_t)r0 * D + dlo];
            afr[kc][1] = *(const uint32_t*)&qT[(size_t)r1 * D + dlo];
            afr[kc][2] = *(const uint32_t*)&qT[(size_t)r0 * D + dhi];
            afr[kc][3] = *(const uint32_t*)&qT[(size_t)r1 * D + dhi];
        }
        auto posv = [&](int d, int i) {
            return rel_h[(h * D + d) * IMG + (i & 31)]
                 + rel_w[(h * D + d) * IMG + (i >> 5)];
        };
        #pragma unroll
        for (int kc = 0; kc < 4; kc++) {
            int dlo = kc * 16 + 2 * t4, dhi = dlo + 8;
            afr[4 + kc][0] = pack2h(posv(dlo, r0), posv(dlo + 1, r0));
            afr[4 + kc][1] = pack2h(posv(dlo, r1), posv(dlo + 1, r1));
            afr[4 + kc][2] = pack2h(posv(dhi, r0), posv(dhi + 1, r0));
            afr[4 + kc][3] = pack2h(posv(dhi, r1), posv(dhi + 1, r1));
        }
    }

    float m0 = -1e30f, m1 = -1e30f, l0 = 0.f, l1 = 0.f;
    float o_acc[8][4] = {};

    for (int ti = 0; ti < 16; ti++) {
        const int bufw = (ti & 1) * BUF_WORDS;
        if (ti < 15) {
            issue((ti + 1) * 64, ((ti + 1) & 1) * BUF_WORDS);
            cpa_commit();
            cpa_wait<1>();
        } else {
            cpa_wait<0>();
        }
        __syncthreads();

        const uint32_t* Bb = smem + bufw;
        const uint32_t* Vb = smem + bufw + KQ_WORDS;

        // ---- S = A B (warp tile 16 x 64), k = 128 in 8 chunks
        float s[8][4] = {};
        #pragma unroll
        for (int kc = 0; kc < 8; kc++) {
            #pragma unroll
            for (int jf = 0; jf < 8; jf++) {
                uint32_t b0 = Bb[(jf * 8 + g) * SKQ + kc * 8 + t4];
                uint32_t b1 = Bb[(jf * 8 + g) * SKQ + kc * 8 + 4 + t4];
                mma_f16(s[jf], afr[kc][0], afr[kc][1], afr[kc][2], afr[kc][3],
                        b0, b1);
            }
        }

        // ---- Online softmax (warp-local; rows g and g+8)
        float mx0 = -1e30f, mx1 = -1e30f;
        #pragma unroll
        for (int jf = 0; jf < 8; jf++) {
            mx0 = fmaxf(mx0, fmaxf(s[jf][0], s[jf][1]));
            mx1 = fmaxf(mx1, fmaxf(s[jf][2], s[jf][3]));
        }
        #pragma unroll
        for (int off = 1; off <= 2; off <<= 1) {
            mx0 = fmaxf(mx0, __shfl_xor_sync(0xffffffffu, mx0, off));
            mx1 = fmaxf(mx1, __shfl_xor_sync(0xffffffffu, mx1, off));
        }
        float mn0 = fmaxf(m0, mx0), mn1 = fmaxf(m1, mx1);
        float sc0 = __expf(m0 - mn0), sc1 = __expf(m1 - mn1);
        float ls0 = 0.f, ls1 = 0.f;
        uint32_t ph[8][2];
        #pragma unroll
        for (int jf = 0; jf < 8; jf++) {
            float p0 = __expf(s[jf][0] - mn0);
            float p1 = __expf(s[jf][1] - mn0);
            float p2 = __expf(s[jf][2] - mn1);
            float p3 = __expf(s[jf][3] - mn1);
            uint32_t lo = pack2h(p0, p1);
            uint32_t hi = pack2h(p2, p3);
            ph[jf][0] = lo; ph[jf][1] = hi;
            float2 f0 = __half22float2(*(__half2*)&lo);
            float2 f1 = __half22float2(*(__half2*)&hi);
            ls0 += f0.x + f0.y;
            ls1 += f1.x + f1.y;
        }
        #pragma unroll
        for (int off = 1; off <= 2; off <<= 1) {
            ls0 += __shfl_xor_sync(0xffffffffu, ls0, off);
            ls1 += __shfl_xor_sync(0xffffffffu, ls1, off);
        }
        l0 = l0 * sc0 + ls0;
        l1 = l1 * sc1 + ls1;
        m0 = mn0; m1 = mn1;
        #pragma unroll
        for (int df = 0; df < 8; df++) {
            o_acc[df][0] *= sc0; o_acc[df][1] *= sc0;
            o_acc[df][2] *= sc1; o_acc[df][3] *= sc1;
        }

        // ---- PV: O[i,dd] += P[i,j] V[dd,j]
        #pragma unroll
        for (int jc = 0; jc < 4; jc++) {
            uint32_t a0 = ph[2 * jc][0],     a1 = ph[2 * jc][1];
            uint32_t a2 = ph[2 * jc + 1][0], a3 = ph[2 * jc + 1][1];
            #pragma unroll
            for (int df = 0; df < 8; df++) {
                uint32_t b0 = Vb[(df * 8 + g) * SVW + jc * 8 + t4];
                uint32_t b1 = Vb[(df * 8 + g) * SVW + jc * 8 + 4 + t4];
                mma_f16(o_acc[df], a0, a1, a2, a3, b0, b1);
            }
        }
        __syncthreads();
    }

    // ---- Normalize, stage to smem (alias buffers), coalesced +x write
    float* Os = (float*)smem;
    float inv0 = 1.f / l0, inv1 = 1.f / l1;
    #pragma unroll
    for (int df = 0; df < 8; df++) {
        int dd = df * 8 + 2 * t4;
        Os[(iw + g) * OS_STRIDE + dd]         = o_acc[df][0] * inv0;
        Os[(iw + g) * OS_STRIDE + dd + 1]     = o_acc[df][1] * inv0;
        Os[(iw + g + 8) * OS_STRIDE + dd]     = o_acc[df][2] * inv1;
        Os[(iw + g + 8) * OS_STRIDE + dd + 1] = o_acc[df][3] * inv1;
    }
    __syncthreads();

    for (int idx = t; idx < 128 * 64; idx += 256) {
        int dd = idx >> 7, mm = idx & 127;
        size_t gi = ((size_t)(b * C) + h * D + dd) * N + i0 + mm;
        out[gi] = Os[mm * OS_STRIDE + dd] + x[gi];
    }
}

// ---------------------------------------------------------------------------
extern "C" void kernel_launch(void* const* d_in, const int* in_sizes, int n_in,
                              void* d_out, int out_size)
{
    const float* x     = (const float*)d_in[0];
    const float* Wq    = (const float*)d_in[1];
    const float* bq    = (const float*)d_in[2];
    const float* Wk    = (const float*)d_in[3];
    const float* bk    = (const float*)d_in[4];
    const float* Wv    = (const float*)d_in[5];
    const float* bv    = (const float*)d_in[6];
    const float* rel_h = (const float*)d_in[7];
    const float* rel_w = (const float*)d_in[8];
    // d_in[9] (reg_qk) and d_in[10] (reg_v) are dead: that group is dropped
    // by out[:, :head].
    float* out = (float*)d_out;

    static bool attr_set = false;
    if (!attr_set) {
        cudaFuncSetAttribute(qkv_f16,
                             cudaFuncAttributeMaxDynamicSharedMemorySize, SMEM_QKV);
        cudaFuncSetAttribute(attn_f16,
                             cudaFuncAttributeMaxDynamicSharedMemorySize, SMEM_ATTN);
        attr_set = true;
    }

    cvt_w<<<dim3(C * C / 1024, 3), 256>>>(Wq, Wk, Wv);
    cvt_xT<<<dim3(N / 32, C / 32, B), 256>>>(x);

    dim3 grid1(N / 128, C / 128, 3 * B);
    qkv_f16<<<grid1, 256, SMEM_QKV>>>(bq, bk, bv);

    dim3 grid2(N / 128, HEAD, B);
    attn_f16<<<grid2, 256, SMEM_ATTN>>>(x, rel_h, rel_w, out);
}